// round 11
// baseline (speedup 1.0000x reference)
#include <cuda_runtime.h>
#include <cstdint>

#define NN   100000
#define EMAX 1600000
#define F    16

typedef unsigned long long ull;

// ---------------- scratch (static __device__, no allocs) ----------------
__device__ int g_deg[NN];
__device__ int g_cur[NN];
__device__ int g_off[NN + 1];
__device__ int g_bsum[128];
__device__ __align__(16) int2  g_sd[EMAX];                 // sorted (src,dst)
__device__ __align__(16) float g_eas[(size_t)EMAX * 8];    // sorted edge_attr
__device__ __align__(16) float g_P1[NN * F];               // conv1 src-partial (bias+src rows)
__device__ __align__(16) float g_P2[NN * F];               // conv2 src-partial (bias+src rows)
__device__ __align__(16) float g_h1[NN * F];
__device__ __align__(16) float g_h2[NN * F];
__device__ int g_idx64;

// ---------------- weights in constant memory ----------------
__constant__ __align__(16) float c1w1[16 * F];
__constant__ __align__(16) float c1b1[F];
__constant__ __align__(16) float c1w2[F * F];
__constant__ __align__(16) float c1b2[F];
__constant__ __align__(16) float c2w1[40 * F];
__constant__ __align__(16) float c2b1[F];
__constant__ __align__(16) float c2w2[F * F];
__constant__ __align__(16) float c2b2[F];
__constant__ __align__(16) float clw1[F * F];
__constant__ __align__(16) float clb1[F];
__constant__ __align__(16) float clw2[F];
__constant__ float clb2[1];

// ---------------- f32x2 packed helpers ----------------
__device__ __forceinline__ ull pk2(float a, float b) {
    ull r; asm("mov.b64 %0, {%1, %2};" : "=l"(r) : "f"(a), "f"(b)); return r;
}
__device__ __forceinline__ ull bcast2(float a) {
    ull r; asm("mov.b64 %0, {%1, %1};" : "=l"(r) : "f"(a)); return r;
}
__device__ __forceinline__ void upk2(ull v, float& a, float& b) {
    asm("mov.b64 {%0, %1}, %2;" : "=f"(a), "=f"(b) : "l"(v));
}
__device__ __forceinline__ ull fma2(ull a, ull b, ull c) {
    ull d; asm("fma.rn.f32x2 %0, %1, %2, %3;" : "=l"(d) : "l"(a), "l"(b), "l"(c)); return d;
}

// ---------------- preprocessing ----------------
__global__ void detect_kernel(const void* ei, int N) {
    const long long* p64 = (const long long*)ei;
    bool ok = true;
#pragma unroll
    for (int k = 0; k < 4; k++) {
        long long v = p64[k];
        if (v < 0 || v >= N) ok = false;
    }
    g_idx64 = ok ? 1 : 0;
}

// zero deg + h1 + h2
__global__ void zero_kernel(int N) {
    int i = blockIdx.x * blockDim.x + threadIdx.x;
    if (i < N) g_deg[i] = 0;
    int n4 = N * 4;
    if (i < n4) {
        reinterpret_cast<float4*>(g_h1)[i] = make_float4(0.f, 0.f, 0.f, 0.f);
        reinterpret_cast<float4*>(g_h2)[i] = make_float4(0.f, 0.f, 0.f, 0.f);
    }
}

__global__ void hist_kernel(const void* __restrict__ ei, int E) {
    int e = blockIdx.x * blockDim.x + threadIdx.x;
    if (e >= E) return;
    int s = g_idx64 ? (int)((const long long*)ei)[e] : ((const int*)ei)[e];
    atomicAdd(&g_deg[s], 1);
}

__global__ void __launch_bounds__(1024) scan_blocks_kernel(int n) {
    __shared__ int wsum[32];
    int i = blockIdx.x * 1024 + threadIdx.x;
    int lane = threadIdx.x & 31;
    int wid  = threadIdx.x >> 5;
    int v = (i < n) ? g_deg[i] : 0;
    int s = v;
#pragma unroll
    for (int o = 1; o < 32; o <<= 1) {
        int t = __shfl_up_sync(~0u, s, o);
        if (lane >= o) s += t;
    }
    if (lane == 31) wsum[wid] = s;
    __syncthreads();
    if (wid == 0) {
        int ws = wsum[lane];
#pragma unroll
        for (int o = 1; o < 32; o <<= 1) {
            int t = __shfl_up_sync(~0u, ws, o);
            if (lane >= o) ws += t;
        }
        wsum[lane] = ws;
    }
    __syncthreads();
    int excl = s - v + (wid > 0 ? wsum[wid - 1] : 0);
    if (i < n) g_off[i] = excl;
    if (threadIdx.x == 1023) g_bsum[blockIdx.x] = wsum[31];
}

__global__ void __launch_bounds__(128) scan_tops_kernel(int nb) {
    __shared__ int wsum[4];
    int lane = threadIdx.x & 31;
    int wid  = threadIdx.x >> 5;
    int v = (threadIdx.x < nb) ? g_bsum[threadIdx.x] : 0;
    int s = v;
#pragma unroll
    for (int o = 1; o < 32; o <<= 1) {
        int t = __shfl_up_sync(~0u, s, o);
        if (lane >= o) s += t;
    }
    if (lane == 31) wsum[wid] = s;
    __syncthreads();
    int base = 0;
#pragma unroll
    for (int k = 0; k < 4; k++) if (k < wid) base += wsum[k];
    if (threadIdx.x < nb) g_bsum[threadIdx.x] = base + s - v;
}

__global__ void __launch_bounds__(1024) add_offsets_kernel(int n, int E) {
    int i = blockIdx.x * 1024 + threadIdx.x;
    if (i < n) g_cur[i] = g_off[i] + g_bsum[blockIdx.x];
}

__global__ void scatter_kernel(const void* __restrict__ ei,
                               const float* __restrict__ ea, int E) {
    int e = blockIdx.x * blockDim.x + threadIdx.x;
    if (e >= E) return;
    int s, d;
    if (g_idx64) {
        const long long* p = (const long long*)ei;
        s = (int)p[e]; d = (int)p[(size_t)E + e];
    } else {
        const int* p = (const int*)ei;
        s = p[e]; d = p[(size_t)E + e];
    }
    int pos = atomicAdd(&g_cur[s], 1);
    g_sd[pos] = make_int2(s, d);
    float4 a0 = *(const float4*)(ea + (size_t)e * 8);
    float4 a1 = *(const float4*)(ea + (size_t)e * 8 + 4);
    *(float4*)(g_eas + (size_t)pos * 8)     = a0;
    *(float4*)(g_eas + (size_t)pos * 8 + 4) = a1;
}

// ---------------- P1: conv1 src-partial per node ----------------
__global__ void __launch_bounds__(256) p1_kernel(const float* __restrict__ x, int N) {
    int n = blockIdx.x * blockDim.x + threadIdx.x;
    if (n >= N) return;
    const ull* w1p = reinterpret_cast<const ull*>(c1w1);
    float4 xv = *(const float4*)(x + (size_t)n * 4);
    float in[4] = {xv.x, xv.y, xv.z, xv.w};
    ull H[8];
#pragma unroll
    for (int k = 0; k < 8; k++) H[k] = pk2(c1b1[2*k], c1b1[2*k+1]);
#pragma unroll
    for (int i = 0; i < 4; i++) {
        ull vv = bcast2(in[i]);
#pragma unroll
        for (int k = 0; k < 8; k++) H[k] = fma2(vv, w1p[i*8 + k], H[k]);
    }
    ull* out = (ull*)(g_P1 + (size_t)n * F);
#pragma unroll
    for (int k = 0; k < 8; k++) out[k] = H[k];
}

// ---------------- P2: conv2 src-partial per node ----------------
__global__ void __launch_bounds__(256) p2_kernel(int N) {
    int n = blockIdx.x * blockDim.x + threadIdx.x;
    if (n >= N) return;
    const ull* w1p = reinterpret_cast<const ull*>(c2w1);
    ull H[8];
#pragma unroll
    for (int k = 0; k < 8; k++) H[k] = pk2(c2b1[2*k], c2b1[2*k+1]);
    const float4* ph = (const float4*)(g_h1 + (size_t)n * F);
#pragma unroll
    for (int q = 0; q < 4; q++) {
        float4 v = ph[q];
        float hv[4] = {v.x, v.y, v.z, v.w};
#pragma unroll
        for (int r = 0; r < 4; r++) {
            ull vv = bcast2(hv[r]);
            int i = q * 4 + r;
#pragma unroll
            for (int k = 0; k < 8; k++) H[k] = fma2(vv, w1p[i*8 + k], H[k]);
        }
    }
    ull* out = (ull*)(g_P2 + (size_t)n * F);
#pragma unroll
    for (int k = 0; k < 8; k++) out[k] = H[k];
}

// ---------------- warp-segmented max (shfl scan) + tail atomics ----------------
__device__ __forceinline__ void seg_max_commit(int s, float* o, float* hout) {
    int lane = threadIdx.x & 31;
#pragma unroll
    for (int off = 1; off < 32; off <<= 1) {
        int so = __shfl_up_sync(~0u, s, off);
        bool merge = (lane >= off) && (so == s);
#pragma unroll
        for (int f = 0; f < F; f++) {
            float v = __shfl_up_sync(~0u, o[f], off);
            if (merge) o[f] = fmaxf(o[f], v);
        }
    }
    int snext = __shfl_down_sync(~0u, s, 1);
    bool tail = (lane == 31) || (snext != s);
    if (tail) {
        int* hp = (int*)(hout + (size_t)s * F);
#pragma unroll
        for (int f = 0; f < F; f++)
            atomicMax(hp + f, __float_as_int(fmaxf(o[f], 0.f)));
    }
}

// ---------------- conv edge kernels: 2 edges per lane, loads front-batched ----------------
__global__ void __launch_bounds__(256) conv1_edge_kernel(const float* __restrict__ x, int E) {
    int warp = (blockIdx.x * blockDim.x + threadIdx.x) >> 5;
    int lane = threadIdx.x & 31;
    int p0 = warp * 64 + lane;
    int p1 = p0 + 32;
    p0 = min(p0, E - 1);   // duplicates harmless for max
    p1 = min(p1, E - 1);

    const ull* w1p = reinterpret_cast<const ull*>(c1w1);
    const ull* w2p = reinterpret_cast<const ull*>(c1w2);

    int2 sd0 = g_sd[p0];
    int2 sd1 = g_sd[p1];

    // front-batch ALL loads for both edges
    ull H0[8], H1[8];
    {
        const ull* Pa = (const ull*)(g_P1 + (size_t)sd0.x * F);
        const ull* Pb = (const ull*)(g_P1 + (size_t)sd1.x * F);
#pragma unroll
        for (int k = 0; k < 8; k++) { H0[k] = Pa[k]; H1[k] = Pb[k]; }
    }
    float4 xj0 = *(const float4*)(x + (size_t)sd0.y * 4);
    float4 xj1 = *(const float4*)(x + (size_t)sd1.y * 4);
    float4 a00 = *(const float4*)(g_eas + (size_t)p0 * 8);
    float4 a01 = *(const float4*)(g_eas + (size_t)p0 * 8 + 4);
    float4 a10 = *(const float4*)(g_eas + (size_t)p1 * 8);
    float4 a11 = *(const float4*)(g_eas + (size_t)p1 * 8 + 4);

    // ---- edge 0 ----
    {
        float in[12] = {xj0.x, xj0.y, xj0.z, xj0.w,
                        a00.x, a00.y, a00.z, a00.w, a01.x, a01.y, a01.z, a01.w};
#pragma unroll
        for (int i = 0; i < 12; i++) {
            ull vv = bcast2(in[i]);
#pragma unroll
            for (int k = 0; k < 8; k++) H0[k] = fma2(vv, w1p[(4+i)*8 + k], H0[k]);
        }
        ull O[8];
#pragma unroll
        for (int k = 0; k < 8; k++) O[k] = pk2(c1b2[2*k], c1b2[2*k+1]);
#pragma unroll
        for (int k = 0; k < 8; k++) {
            float a, b; upk2(H0[k], a, b);
            a = fmaxf(a, 0.f); b = fmaxf(b, 0.f);
            ull va = bcast2(a), vb = bcast2(b);
#pragma unroll
            for (int m = 0; m < 8; m++) O[m] = fma2(va, w2p[(2*k)*8 + m], O[m]);
#pragma unroll
            for (int m = 0; m < 8; m++) O[m] = fma2(vb, w2p[(2*k+1)*8 + m], O[m]);
        }
        float o[F];
#pragma unroll
        for (int m = 0; m < 8; m++) upk2(O[m], o[2*m], o[2*m+1]);
        seg_max_commit(sd0.x, o, g_h1);
    }

    // ---- edge 1 ----
    {
        float in[12] = {xj1.x, xj1.y, xj1.z, xj1.w,
                        a10.x, a10.y, a10.z, a10.w, a11.x, a11.y, a11.z, a11.w};
#pragma unroll
        for (int i = 0; i < 12; i++) {
            ull vv = bcast2(in[i]);
#pragma unroll
            for (int k = 0; k < 8; k++) H1[k] = fma2(vv, w1p[(4+i)*8 + k], H1[k]);
        }
        ull O[8];
#pragma unroll
        for (int k = 0; k < 8; k++) O[k] = pk2(c1b2[2*k], c1b2[2*k+1]);
#pragma unroll
        for (int k = 0; k < 8; k++) {
            float a, b; upk2(H1[k], a, b);
            a = fmaxf(a, 0.f); b = fmaxf(b, 0.f);
            ull va = bcast2(a), vb = bcast2(b);
#pragma unroll
            for (int m = 0; m < 8; m++) O[m] = fma2(va, w2p[(2*k)*8 + m], O[m]);
#pragma unroll
            for (int m = 0; m < 8; m++) O[m] = fma2(vb, w2p[(2*k+1)*8 + m], O[m]);
        }
        float o[F];
#pragma unroll
        for (int m = 0; m < 8; m++) upk2(O[m], o[2*m], o[2*m+1]);
        seg_max_commit(sd1.x, o, g_h1);
    }
}

__global__ void __launch_bounds__(256) conv2_edge_kernel(int E) {
    int warp = (blockIdx.x * blockDim.x + threadIdx.x) >> 5;
    int lane = threadIdx.x & 31;
    int p0 = warp * 64 + lane;
    int p1 = p0 + 32;
    p0 = min(p0, E - 1);
    p1 = min(p1, E - 1);

    const ull* w1p = reinterpret_cast<const ull*>(c2w1);
    const ull* w2p = reinterpret_cast<const ull*>(c2w2);

    int2 sd0 = g_sd[p0];
    int2 sd1 = g_sd[p1];

    // front-batch ALL loads for both edges
    ull H0[8], H1[8];
    {
        const ull* Pa = (const ull*)(g_P2 + (size_t)sd0.x * F);
        const ull* Pb = (const ull*)(g_P2 + (size_t)sd1.x * F);
#pragma unroll
        for (int k = 0; k < 8; k++) { H0[k] = Pa[k]; H1[k] = Pb[k]; }
    }
    float4 d00, d01, d02, d03, d10, d11, d12, d13;
    {
        const float4* pa = (const float4*)(g_h1 + (size_t)sd0.y * F);
        const float4* pb = (const float4*)(g_h1 + (size_t)sd1.y * F);
        d00 = pa[0]; d01 = pa[1]; d02 = pa[2]; d03 = pa[3];
        d10 = pb[0]; d11 = pb[1]; d12 = pb[2]; d13 = pb[3];
    }
    float4 a00 = *(const float4*)(g_eas + (size_t)p0 * 8);
    float4 a01 = *(const float4*)(g_eas + (size_t)p0 * 8 + 4);
    float4 a10 = *(const float4*)(g_eas + (size_t)p1 * 8);
    float4 a11 = *(const float4*)(g_eas + (size_t)p1 * 8 + 4);

    // ---- edge 0 ----
    {
        float in[24] = {d00.x, d00.y, d00.z, d00.w, d01.x, d01.y, d01.z, d01.w,
                        d02.x, d02.y, d02.z, d02.w, d03.x, d03.y, d03.z, d03.w,
                        a00.x, a00.y, a00.z, a00.w, a01.x, a01.y, a01.z, a01.w};
#pragma unroll
        for (int i = 0; i < 24; i++) {
            ull vv = bcast2(in[i]);
#pragma unroll
            for (int k = 0; k < 8; k++) H0[k] = fma2(vv, w1p[(16+i)*8 + k], H0[k]);
        }
        ull O[8];
#pragma unroll
        for (int k = 0; k < 8; k++) O[k] = pk2(c2b2[2*k], c2b2[2*k+1]);
#pragma unroll
        for (int k = 0; k < 8; k++) {
            float a, b; upk2(H0[k], a, b);
            a = fmaxf(a, 0.f); b = fmaxf(b, 0.f);
            ull va = bcast2(a), vb = bcast2(b);
#pragma unroll
            for (int m = 0; m < 8; m++) O[m] = fma2(va, w2p[(2*k)*8 + m], O[m]);
#pragma unroll
            for (int m = 0; m < 8; m++) O[m] = fma2(vb, w2p[(2*k+1)*8 + m], O[m]);
        }
        float o[F];
#pragma unroll
        for (int m = 0; m < 8; m++) upk2(O[m], o[2*m], o[2*m+1]);
        seg_max_commit(sd0.x, o, g_h2);
    }

    // ---- edge 1 ----
    {
        float in[24] = {d10.x, d10.y, d10.z, d10.w, d11.x, d11.y, d11.z, d11.w,
                        d12.x, d12.y, d12.z, d12.w, d13.x, d13.y, d13.z, d13.w,
                        a10.x, a10.y, a10.z, a10.w, a11.x, a11.y, a11.z, a11.w};
#pragma unroll
        for (int i = 0; i < 24; i++) {
            ull vv = bcast2(in[i]);
#pragma unroll
            for (int k = 0; k < 8; k++) H1[k] = fma2(vv, w1p[(16+i)*8 + k], H1[k]);
        }
        ull O[8];
#pragma unroll
        for (int k = 0; k < 8; k++) O[k] = pk2(c2b2[2*k], c2b2[2*k+1]);
#pragma unroll
        for (int k = 0; k < 8; k++) {
            float a, b; upk2(H1[k], a, b);
            a = fmaxf(a, 0.f); b = fmaxf(b, 0.f);
            ull va = bcast2(a), vb = bcast2(b);
#pragma unroll
            for (int m = 0; m < 8; m++) O[m] = fma2(va, w2p[(2*k)*8 + m], O[m]);
#pragma unroll
            for (int m = 0; m < 8; m++) O[m] = fma2(vb, w2p[(2*k+1)*8 + m], O[m]);
        }
        float o[F];
#pragma unroll
        for (int m = 0; m < 8; m++) upk2(O[m], o[2*m], o[2*m+1]);
        seg_max_commit(sd1.x, o, g_h2);
    }
}

// ---------------- final node MLP (packed) ----------------
__global__ void __launch_bounds__(256) node_mlp_kernel(float* __restrict__ out, int n) {
    int i = blockIdx.x * blockDim.x + threadIdx.x;
    if (i >= n) return;

    const ull* w1p = reinterpret_cast<const ull*>(clw1);

    ull H[8];
#pragma unroll
    for (int k = 0; k < 8; k++) H[k] = pk2(clb1[2*k], clb1[2*k+1]);

    const float4* ph = (const float4*)(g_h2 + (size_t)i * F);
#pragma unroll
    for (int q = 0; q < 4; q++) {
        float4 v = ph[q];
        float hv[4] = {v.x, v.y, v.z, v.w};
#pragma unroll
        for (int r = 0; r < 4; r++) {
            ull vv = bcast2(hv[r]);
            int kk = q * 4 + r;
#pragma unroll
            for (int k = 0; k < 8; k++) H[k] = fma2(vv, w1p[kk*8 + k], H[k]);
        }
    }

    float acc = clb2[0];
#pragma unroll
    for (int k = 0; k < 8; k++) {
        float a, b; upk2(H[k], a, b);
        acc += fmaxf(a, 0.f) * clw2[2*k] + fmaxf(b, 0.f) * clw2[2*k+1];
    }
    out[i] = acc;
}

// ---------------- launch ----------------
extern "C" void kernel_launch(void* const* d_in, const int* in_sizes, int n_in,
                              void* d_out, int out_size)
{
    const float* x  = (const float*)d_in[0];
    const void*  ei = d_in[1];
    const float* ea = (const float*)d_in[2];

    int N = in_sizes[0] / 4;   // x is [N,4]
    int E = in_sizes[2] / 8;   // edge_attr is [E,8]
    float* out = (float*)d_out;

    cudaMemcpyToSymbolAsync(c1w1, d_in[3],  16 * F * sizeof(float), 0, cudaMemcpyDeviceToDevice);
    cudaMemcpyToSymbolAsync(c1b1, d_in[4],  F * sizeof(float),      0, cudaMemcpyDeviceToDevice);
    cudaMemcpyToSymbolAsync(c1w2, d_in[5],  F * F * sizeof(float),  0, cudaMemcpyDeviceToDevice);
    cudaMemcpyToSymbolAsync(c1b2, d_in[6],  F * sizeof(float),      0, cudaMemcpyDeviceToDevice);
    cudaMemcpyToSymbolAsync(c2w1, d_in[7],  40 * F * sizeof(float), 0, cudaMemcpyDeviceToDevice);
    cudaMemcpyToSymbolAsync(c2b1, d_in[8],  F * sizeof(float),      0, cudaMemcpyDeviceToDevice);
    cudaMemcpyToSymbolAsync(c2w2, d_in[9],  F * F * sizeof(float),  0, cudaMemcpyDeviceToDevice);
    cudaMemcpyToSymbolAsync(c2b2, d_in[10], F * sizeof(float),      0, cudaMemcpyDeviceToDevice);
    cudaMemcpyToSymbolAsync(clw1, d_in[11], F * F * sizeof(float),  0, cudaMemcpyDeviceToDevice);
    cudaMemcpyToSymbolAsync(clb1, d_in[12], F * sizeof(float),      0, cudaMemcpyDeviceToDevice);
    cudaMemcpyToSymbolAsync(clw2, d_in[13], F * sizeof(float),      0, cudaMemcpyDeviceToDevice);
    cudaMemcpyToSymbolAsync(clb2, d_in[14], 1 * sizeof(float),      0, cudaMemcpyDeviceToDevice);

    detect_kernel<<<1, 1>>>(ei, N);
    zero_kernel<<<(N * 4 + 255) / 256, 256>>>(N);

    int eblocks = (E + 255) / 256;
    hist_kernel<<<eblocks, 256>>>(ei, E);

    int sblocks = (N + 1023) / 1024;
    scan_blocks_kernel<<<sblocks, 1024>>>(N);
    scan_tops_kernel<<<1, 128>>>(sblocks);
    add_offsets_kernel<<<sblocks, 1024>>>(N, E);

    scatter_kernel<<<eblocks, 256>>>(ei, ea, E);
    p1_kernel<<<(N + 255) / 256, 256>>>(x, N);

    int e2blocks = (E + 511) / 512;    // 2 edges per thread
    conv1_edge_kernel<<<e2blocks, 256>>>(x, E);
    p2_kernel<<<(N + 255) / 256, 256>>>(N);
    conv2_edge_kernel<<<e2blocks, 256>>>(E);

    node_mlp_kernel<<<(N + 255) / 256, 256>>>(out, N);
}

// round 12
// speedup vs baseline: 1.1246x; 1.1246x over previous
#include <cuda_runtime.h>
#include <cstdint>

#define NN   100000
#define EMAX 1600000
#define F    16

typedef unsigned long long ull;

// ---------------- scratch (static __device__, no allocs) ----------------
__device__ int g_deg[NN];
__device__ int g_cur[NN];
__device__ int g_off[NN + 1];
__device__ int g_bsum[128];
__device__ __align__(16) int2  g_sd[EMAX];                 // sorted (src,dst)
__device__ __align__(16) float g_eas[(size_t)EMAX * 8];    // sorted edge_attr
__device__ __align__(16) float g_P1[NN * F];               // conv1 src-partial (bias+src rows)
__device__ __align__(16) float g_P2[NN * F];               // conv2 src-partial (bias+src rows)
__device__ __align__(16) float g_h1[NN * F];
__device__ __align__(16) float g_h2[NN * F];
__device__ __align__(16) float g_stage[1792];              // weight staging

// ---------------- all weights in ONE constant array ----------------
// layout (float offsets):
#define OC1W1 0      // 256
#define OC1B1 256    // 16
#define OC1W2 272    // 256
#define OC1B2 528    // 16
#define OC2W1 544    // 640
#define OC2B1 1184   // 16
#define OC2W2 1200   // 256
#define OC2B2 1456   // 16
#define OCLW1 1472   // 256
#define OCLB1 1728   // 16
#define OCLW2 1744   // 16
#define OCLB2 1760   // 1
#define CWTOT 1761
__constant__ __align__(16) float cw[1792];

// ---------------- f32x2 packed helpers ----------------
__device__ __forceinline__ ull pk2(float a, float b) {
    ull r; asm("mov.b64 %0, {%1, %2};" : "=l"(r) : "f"(a), "f"(b)); return r;
}
__device__ __forceinline__ ull bcast2(float a) {
    ull r; asm("mov.b64 %0, {%1, %1};" : "=l"(r) : "f"(a)); return r;
}
__device__ __forceinline__ void upk2(ull v, float& a, float& b) {
    asm("mov.b64 {%0, %1}, %2;" : "=f"(a), "=f"(b) : "l"(v));
}
__device__ __forceinline__ ull fma2(ull a, ull b, ull c) {
    ull d; asm("fma.rn.f32x2 %0, %1, %2, %3;" : "=l"(d) : "l"(a), "l"(b), "l"(c)); return d;
}

// ---------------- per-block int64 detection ----------------
__device__ __forceinline__ bool block_idx64(const void* ei, int N, int* sflag) {
    if (threadIdx.x == 0) {
        const long long* p64 = (const long long*)ei;
        bool ok = true;
#pragma unroll
        for (int k = 0; k < 4; k++) {
            long long v = p64[k];
            if (v < 0 || v >= N) ok = false;
        }
        *sflag = ok ? 1 : 0;
    }
    __syncthreads();
    return *sflag != 0;
}

// ---------------- weight staging: 12 buffers -> one device array ----------------
__global__ void __launch_bounds__(256) stage_weights_kernel(
    const float* w0, const float* w1, const float* w2, const float* w3,
    const float* w4, const float* w5, const float* w6, const float* w7,
    const float* w8, const float* w9, const float* w10, const float* w11)
{
    int t = threadIdx.x;
    for (int i = t; i < 256; i += 256) g_stage[OC1W1 + i] = w0[i];
    if (t < 16)  g_stage[OC1B1 + t] = w1[t];
    for (int i = t; i < 256; i += 256) g_stage[OC1W2 + i] = w2[i];
    if (t < 16)  g_stage[OC1B2 + t] = w3[t];
    for (int i = t; i < 640; i += 256) g_stage[OC2W1 + i] = w4[i];
    if (t < 16)  g_stage[OC2B1 + t] = w5[t];
    for (int i = t; i < 256; i += 256) g_stage[OC2W2 + i] = w6[i];
    if (t < 16)  g_stage[OC2B2 + t] = w7[t];
    for (int i = t; i < 256; i += 256) g_stage[OCLW1 + i] = w8[i];
    if (t < 16)  g_stage[OCLB1 + t] = w9[t];
    if (t < 16)  g_stage[OCLW2 + t] = w10[t];
    if (t == 0)  g_stage[OCLB2] = w11[0];
}

// ---------------- zero (deg,h1,h2) + P1 fused ----------------
__global__ void __launch_bounds__(256) zero_p1_kernel(const float* __restrict__ x, int N) {
    int i = blockIdx.x * blockDim.x + threadIdx.x;
    int n4 = N * 4;
    if (i < n4) {
        reinterpret_cast<float4*>(g_h1)[i] = make_float4(0.f, 0.f, 0.f, 0.f);
        reinterpret_cast<float4*>(g_h2)[i] = make_float4(0.f, 0.f, 0.f, 0.f);
    }
    if (i < N) {
        g_deg[i] = 0;
        const ull* w1p = reinterpret_cast<const ull*>(cw + OC1W1);
        float4 xv = *(const float4*)(x + (size_t)i * 4);
        float in[4] = {xv.x, xv.y, xv.z, xv.w};
        ull H[8];
#pragma unroll
        for (int k = 0; k < 8; k++) H[k] = pk2(cw[OC1B1 + 2*k], cw[OC1B1 + 2*k+1]);
#pragma unroll
        for (int r = 0; r < 4; r++) {
            ull vv = bcast2(in[r]);
#pragma unroll
            for (int k = 0; k < 8; k++) H[k] = fma2(vv, w1p[r*8 + k], H[k]);
        }
        ull* out = (ull*)(g_P1 + (size_t)i * F);
#pragma unroll
        for (int k = 0; k < 8; k++) out[k] = H[k];
    }
}

__global__ void hist_kernel(const void* __restrict__ ei, int E, int N) {
    __shared__ int sflag;
    bool idx64 = block_idx64(ei, N, &sflag);
    int e = blockIdx.x * blockDim.x + threadIdx.x;
    if (e >= E) return;
    int s = idx64 ? (int)((const long long*)ei)[e] : ((const int*)ei)[e];
    atomicAdd(&g_deg[s], 1);
}

__global__ void __launch_bounds__(1024) scan_blocks_kernel(int n) {
    __shared__ int wsum[32];
    int i = blockIdx.x * 1024 + threadIdx.x;
    int lane = threadIdx.x & 31;
    int wid  = threadIdx.x >> 5;
    int v = (i < n) ? g_deg[i] : 0;
    int s = v;
#pragma unroll
    for (int o = 1; o < 32; o <<= 1) {
        int t = __shfl_up_sync(~0u, s, o);
        if (lane >= o) s += t;
    }
    if (lane == 31) wsum[wid] = s;
    __syncthreads();
    if (wid == 0) {
        int ws = wsum[lane];
#pragma unroll
        for (int o = 1; o < 32; o <<= 1) {
            int t = __shfl_up_sync(~0u, ws, o);
            if (lane >= o) ws += t;
        }
        wsum[lane] = ws;
    }
    __syncthreads();
    int excl = s - v + (wid > 0 ? wsum[wid - 1] : 0);
    if (i < n) g_off[i] = excl;
    if (threadIdx.x == 1023) g_bsum[blockIdx.x] = wsum[31];
}

__global__ void __launch_bounds__(128) scan_tops_kernel(int nb) {
    __shared__ int wsum[4];
    int lane = threadIdx.x & 31;
    int wid  = threadIdx.x >> 5;
    int v = (threadIdx.x < nb) ? g_bsum[threadIdx.x] : 0;
    int s = v;
#pragma unroll
    for (int o = 1; o < 32; o <<= 1) {
        int t = __shfl_up_sync(~0u, s, o);
        if (lane >= o) s += t;
    }
    if (lane == 31) wsum[wid] = s;
    __syncthreads();
    int base = 0;
#pragma unroll
    for (int k = 0; k < 4; k++) if (k < wid) base += wsum[k];
    if (threadIdx.x < nb) g_bsum[threadIdx.x] = base + s - v;
}

__global__ void __launch_bounds__(1024) add_offsets_kernel(int n) {
    int i = blockIdx.x * 1024 + threadIdx.x;
    if (i < n) g_cur[i] = g_off[i] + g_bsum[blockIdx.x];
}

__global__ void scatter_kernel(const void* __restrict__ ei,
                               const float* __restrict__ ea, int E, int N) {
    __shared__ int sflag;
    bool idx64 = block_idx64(ei, N, &sflag);
    int e = blockIdx.x * blockDim.x + threadIdx.x;
    if (e >= E) return;
    int s, d;
    if (idx64) {
        const long long* p = (const long long*)ei;
        s = (int)p[e]; d = (int)p[(size_t)E + e];
    } else {
        const int* p = (const int*)ei;
        s = p[e]; d = p[(size_t)E + e];
    }
    int pos = atomicAdd(&g_cur[s], 1);
    g_sd[pos] = make_int2(s, d);
    float4 a0 = *(const float4*)(ea + (size_t)e * 8);
    float4 a1 = *(const float4*)(ea + (size_t)e * 8 + 4);
    *(float4*)(g_eas + (size_t)pos * 8)     = a0;
    *(float4*)(g_eas + (size_t)pos * 8 + 4) = a1;
}

// ---------------- P2: conv2 src-partial per node ----------------
__global__ void __launch_bounds__(256) p2_kernel(int N) {
    int n = blockIdx.x * blockDim.x + threadIdx.x;
    if (n >= N) return;
    const ull* w1p = reinterpret_cast<const ull*>(cw + OC2W1);
    ull H[8];
#pragma unroll
    for (int k = 0; k < 8; k++) H[k] = pk2(cw[OC2B1 + 2*k], cw[OC2B1 + 2*k+1]);
    const float4* ph = (const float4*)(g_h1 + (size_t)n * F);
#pragma unroll
    for (int q = 0; q < 4; q++) {
        float4 v = ph[q];
        float hv[4] = {v.x, v.y, v.z, v.w};
#pragma unroll
        for (int r = 0; r < 4; r++) {
            ull vv = bcast2(hv[r]);
            int i = q * 4 + r;
#pragma unroll
            for (int k = 0; k < 8; k++) H[k] = fma2(vv, w1p[i*8 + k], H[k]);
        }
    }
    ull* out = (ull*)(g_P2 + (size_t)n * F);
#pragma unroll
    for (int k = 0; k < 8; k++) out[k] = H[k];
}

// ---------------- warp-segmented max (shfl scan) + tail atomics ----------------
__device__ __forceinline__ void seg_max_commit(int s, float* o, float* hout) {
    int lane = threadIdx.x & 31;
#pragma unroll
    for (int off = 1; off < 32; off <<= 1) {
        int so = __shfl_up_sync(~0u, s, off);
        bool merge = (lane >= off) && (so == s);
#pragma unroll
        for (int f = 0; f < F; f++) {
            float v = __shfl_up_sync(~0u, o[f], off);
            if (merge) o[f] = fmaxf(o[f], v);
        }
    }
    int snext = __shfl_down_sync(~0u, s, 1);
    bool tail = (lane == 31) || (snext != s);
    if (tail) {
        int* hp = (int*)(hout + (size_t)s * F);
#pragma unroll
        for (int f = 0; f < F; f++)
            atomicMax(hp + f, __float_as_int(fmaxf(o[f], 0.f)));
    }
}

// ---------------- conv edge kernels: one lane = one sorted edge ----------------
__global__ void __launch_bounds__(256) conv1_edge_kernel(const float* __restrict__ x, int E) {
    int p = blockIdx.x * blockDim.x + threadIdx.x;
    p = min(p, E - 1);   // duplicates harmless for max

    const ull* w1p = reinterpret_cast<const ull*>(cw + OC1W1);
    const ull* w2p = reinterpret_cast<const ull*>(cw + OC1W2);

    int2 sd = g_sd[p];
    ull H[8];
    {
        const ull* Pp = (const ull*)(g_P1 + (size_t)sd.x * F);
#pragma unroll
        for (int k = 0; k < 8; k++) H[k] = Pp[k];
    }
    float4 xj = *(const float4*)(x + (size_t)sd.y * 4);
    float4 a0 = *(const float4*)(g_eas + (size_t)p * 8);
    float4 a1 = *(const float4*)(g_eas + (size_t)p * 8 + 4);
    float in[12] = {xj.x, xj.y, xj.z, xj.w,
                    a0.x, a0.y, a0.z, a0.w, a1.x, a1.y, a1.z, a1.w};
#pragma unroll
    for (int i = 0; i < 12; i++) {
        ull vv = bcast2(in[i]);
#pragma unroll
        for (int k = 0; k < 8; k++) H[k] = fma2(vv, w1p[(4+i)*8 + k], H[k]);
    }

    ull O[8];
#pragma unroll
    for (int k = 0; k < 8; k++) O[k] = pk2(cw[OC1B2 + 2*k], cw[OC1B2 + 2*k+1]);
#pragma unroll
    for (int k = 0; k < 8; k++) {
        float a, b; upk2(H[k], a, b);
        a = fmaxf(a, 0.f); b = fmaxf(b, 0.f);
        ull va = bcast2(a), vb = bcast2(b);
#pragma unroll
        for (int m = 0; m < 8; m++) O[m] = fma2(va, w2p[(2*k)*8 + m], O[m]);
#pragma unroll
        for (int m = 0; m < 8; m++) O[m] = fma2(vb, w2p[(2*k+1)*8 + m], O[m]);
    }
    float o[F];
#pragma unroll
    for (int m = 0; m < 8; m++) upk2(O[m], o[2*m], o[2*m+1]);

    seg_max_commit(sd.x, o, g_h1);
}

__global__ void __launch_bounds__(256) conv2_edge_kernel(int E) {
    int p = blockIdx.x * blockDim.x + threadIdx.x;
    p = min(p, E - 1);

    const ull* w1p = reinterpret_cast<const ull*>(cw + OC2W1);
    const ull* w2p = reinterpret_cast<const ull*>(cw + OC2W2);

    int2 sd = g_sd[p];
    ull H[8];
    {
        const ull* Pp = (const ull*)(g_P2 + (size_t)sd.x * F);
#pragma unroll
        for (int k = 0; k < 8; k++) H[k] = Pp[k];
    }
    float in[24];
    {
        const float4* pd = (const float4*)(g_h1 + (size_t)sd.y * F);
#pragma unroll
        for (int q = 0; q < 4; q++) {
            float4 v = pd[q];
            in[q*4+0] = v.x; in[q*4+1] = v.y; in[q*4+2] = v.z; in[q*4+3] = v.w;
        }
        float4 a0 = *(const float4*)(g_eas + (size_t)p * 8);
        float4 a1 = *(const float4*)(g_eas + (size_t)p * 8 + 4);
        in[16] = a0.x; in[17] = a0.y; in[18] = a0.z; in[19] = a0.w;
        in[20] = a1.x; in[21] = a1.y; in[22] = a1.z; in[23] = a1.w;
    }
#pragma unroll
    for (int i = 0; i < 24; i++) {
        ull vv = bcast2(in[i]);
#pragma unroll
        for (int k = 0; k < 8; k++) H[k] = fma2(vv, w1p[(16+i)*8 + k], H[k]);
    }

    ull O[8];
#pragma unroll
    for (int k = 0; k < 8; k++) O[k] = pk2(cw[OC2B2 + 2*k], cw[OC2B2 + 2*k+1]);
#pragma unroll
    for (int k = 0; k < 8; k++) {
        float a, b; upk2(H[k], a, b);
        a = fmaxf(a, 0.f); b = fmaxf(b, 0.f);
        ull va = bcast2(a), vb = bcast2(b);
#pragma unroll
        for (int m = 0; m < 8; m++) O[m] = fma2(va, w2p[(2*k)*8 + m], O[m]);
#pragma unroll
        for (int m = 0; m < 8; m++) O[m] = fma2(vb, w2p[(2*k+1)*8 + m], O[m]);
    }
    float o[F];
#pragma unroll
    for (int m = 0; m < 8; m++) upk2(O[m], o[2*m], o[2*m+1]);

    seg_max_commit(sd.x, o, g_h2);
}

// ---------------- final node MLP (packed) ----------------
__global__ void __launch_bounds__(256) node_mlp_kernel(float* __restrict__ out, int n) {
    int i = blockIdx.x * blockDim.x + threadIdx.x;
    if (i >= n) return;

    const ull* w1p = reinterpret_cast<const ull*>(cw + OCLW1);

    ull H[8];
#pragma unroll
    for (int k = 0; k < 8; k++) H[k] = pk2(cw[OCLB1 + 2*k], cw[OCLB1 + 2*k+1]);

    const float4* ph = (const float4*)(g_h2 + (size_t)i * F);
#pragma unroll
    for (int q = 0; q < 4; q++) {
        float4 v = ph[q];
        float hv[4] = {v.x, v.y, v.z, v.w};
#pragma unroll
        for (int r = 0; r < 4; r++) {
            ull vv = bcast2(hv[r]);
            int kk = q * 4 + r;
#pragma unroll
            for (int k = 0; k < 8; k++) H[k] = fma2(vv, w1p[kk*8 + k], H[k]);
        }
    }

    float acc = cw[OCLB2];
#pragma unroll
    for (int k = 0; k < 8; k++) {
        float a, b; upk2(H[k], a, b);
        acc += fmaxf(a, 0.f) * cw[OCLW2 + 2*k] + fmaxf(b, 0.f) * cw[OCLW2 + 2*k+1];
    }
    out[i] = acc;
}

// ---------------- launch ----------------
extern "C" void kernel_launch(void* const* d_in, const int* in_sizes, int n_in,
                              void* d_out, int out_size)
{
    const float* x  = (const float*)d_in[0];
    const void*  ei = d_in[1];
    const float* ea = (const float*)d_in[2];

    int N = in_sizes[0] / 4;   // x is [N,4]
    int E = in_sizes[2] / 8;   // edge_attr is [E,8]
    float* out = (float*)d_out;

    // 1 kernel + 1 memcpy instead of 12 memcpy nodes
    stage_weights_kernel<<<1, 256>>>(
        (const float*)d_in[3],  (const float*)d_in[4],  (const float*)d_in[5],
        (const float*)d_in[6],  (const float*)d_in[7],  (const float*)d_in[8],
        (const float*)d_in[9],  (const float*)d_in[10], (const float*)d_in[11],
        (const float*)d_in[12], (const float*)d_in[13], (const float*)d_in[14]);
    void* stage_addr = nullptr;
    cudaGetSymbolAddress(&stage_addr, g_stage);
    cudaMemcpyToSymbolAsync(cw, stage_addr, CWTOT * sizeof(float), 0,
                            cudaMemcpyDeviceToDevice);

    zero_p1_kernel<<<(N * 4 + 255) / 256, 256>>>(x, N);

    int eblocks = (E + 255) / 256;
    hist_kernel<<<eblocks, 256>>>(ei, E, N);

    int sblocks = (N + 1023) / 1024;
    scan_blocks_kernel<<<sblocks, 1024>>>(N);
    scan_tops_kernel<<<1, 128>>>(sblocks);
    add_offsets_kernel<<<sblocks, 1024>>>(N);

    scatter_kernel<<<eblocks, 256>>>(ei, ea, E, N);

    conv1_edge_kernel<<<eblocks, 256>>>(x, E);
    p2_kernel<<<(N + 255) / 256, 256>>>(N);
    conv2_edge_kernel<<<eblocks, 256>>>(E);

    node_mlp_kernel<<<(N + 255) / 256, 256>>>(out, N);
}

// round 13
// speedup vs baseline: 1.1710x; 1.0412x over previous
#include <cuda_runtime.h>
#include <cstdint>

#define NN   100000
#define EMAX 1600000
#define F    16

typedef unsigned long long ull;

// ---------------- scratch (static __device__, no allocs) ----------------
__device__ int g_deg[NN];
__device__ int g_cur[NN];
__device__ int g_off[NN + 1];
__device__ int g_bsum[128];
__device__ __align__(16) int2  g_sd[EMAX];                 // sorted (src,dst)
__device__ __align__(16) float g_eas[(size_t)EMAX * 8];    // sorted edge_attr
__device__ __align__(16) float g_P2[NN * F];               // conv2 src-partial (bias+src rows)
__device__ __align__(16) float g_h1[NN * F];
__device__ __align__(16) float g_h2[NN * F];
__device__ __align__(16) float g_stage[1792];              // weight staging

// ---------------- all weights in ONE constant array ----------------
#define OC1W1 0      // 256
#define OC1B1 256    // 16
#define OC1W2 272    // 256
#define OC1B2 528    // 16
#define OC2W1 544    // 640
#define OC2B1 1184   // 16
#define OC2W2 1200   // 256
#define OC2B2 1456   // 16
#define OCLW1 1472   // 256
#define OCLB1 1728   // 16
#define OCLW2 1744   // 16
#define OCLB2 1760   // 1
#define CWTOT 1761
__constant__ __align__(16) float cw[1792];

// ---------------- f32x2 packed helpers ----------------
__device__ __forceinline__ ull pk2(float a, float b) {
    ull r; asm("mov.b64 %0, {%1, %2};" : "=l"(r) : "f"(a), "f"(b)); return r;
}
__device__ __forceinline__ ull bcast2(float a) {
    ull r; asm("mov.b64 %0, {%1, %1};" : "=l"(r) : "f"(a)); return r;
}
__device__ __forceinline__ void upk2(ull v, float& a, float& b) {
    asm("mov.b64 {%0, %1}, %2;" : "=f"(a), "=f"(b) : "l"(v));
}
__device__ __forceinline__ ull fma2(ull a, ull b, ull c) {
    ull d; asm("fma.rn.f32x2 %0, %1, %2, %3;" : "=l"(d) : "l"(a), "l"(b), "l"(c)); return d;
}

// ---------------- per-block int64 detection ----------------
__device__ __forceinline__ bool block_idx64(const void* ei, int N, int* sflag) {
    if (threadIdx.x == 0) {
        const long long* p64 = (const long long*)ei;
        bool ok = true;
#pragma unroll
        for (int k = 0; k < 4; k++) {
            long long v = p64[k];
            if (v < 0 || v >= N) ok = false;
        }
        *sflag = ok ? 1 : 0;
    }
    __syncthreads();
    return *sflag != 0;
}

// ---------------- weight staging: 12 buffers -> one device array ----------------
__global__ void __launch_bounds__(256) stage_weights_kernel(
    const float* w0, const float* w1, const float* w2, const float* w3,
    const float* w4, const float* w5, const float* w6, const float* w7,
    const float* w8, const float* w9, const float* w10, const float* w11)
{
    int t = threadIdx.x;
    for (int i = t; i < 256; i += 256) g_stage[OC1W1 + i] = w0[i];
    if (t < 16)  g_stage[OC1B1 + t] = w1[t];
    for (int i = t; i < 256; i += 256) g_stage[OC1W2 + i] = w2[i];
    if (t < 16)  g_stage[OC1B2 + t] = w3[t];
    for (int i = t; i < 640; i += 256) g_stage[OC2W1 + i] = w4[i];
    if (t < 16)  g_stage[OC2B1 + t] = w5[t];
    for (int i = t; i < 256; i += 256) g_stage[OC2W2 + i] = w6[i];
    if (t < 16)  g_stage[OC2B2 + t] = w7[t];
    for (int i = t; i < 256; i += 256) g_stage[OCLW1 + i] = w8[i];
    if (t < 16)  g_stage[OCLB1 + t] = w9[t];
    if (t < 16)  g_stage[OCLW2 + t] = w10[t];
    if (t == 0)  g_stage[OCLB2] = w11[0];
}

// ---------------- zeroing kernels ----------------
__global__ void zero_h_kernel(int N) {
    int i = blockIdx.x * blockDim.x + threadIdx.x;
    int n4 = N * 4;
    if (i < n4) {
        reinterpret_cast<float4*>(g_h1)[i] = make_float4(0.f, 0.f, 0.f, 0.f);
        reinterpret_cast<float4*>(g_h2)[i] = make_float4(0.f, 0.f, 0.f, 0.f);
    }
}

__global__ void zero_deg_kernel(int N) {
    int i = blockIdx.x * blockDim.x + threadIdx.x;
    if (i < N) g_deg[i] = 0;
}

__global__ void hist_kernel(const void* __restrict__ ei, int E, int N) {
    __shared__ int sflag;
    bool idx64 = block_idx64(ei, N, &sflag);
    int e = blockIdx.x * blockDim.x + threadIdx.x;
    if (e >= E) return;
    int s = idx64 ? (int)((const long long*)ei)[e] : ((const int*)ei)[e];
    atomicAdd(&g_deg[s], 1);
}

__global__ void __launch_bounds__(1024) scan_blocks_kernel(int n) {
    __shared__ int wsum[32];
    int i = blockIdx.x * 1024 + threadIdx.x;
    int lane = threadIdx.x & 31;
    int wid  = threadIdx.x >> 5;
    int v = (i < n) ? g_deg[i] : 0;
    int s = v;
#pragma unroll
    for (int o = 1; o < 32; o <<= 1) {
        int t = __shfl_up_sync(~0u, s, o);
        if (lane >= o) s += t;
    }
    if (lane == 31) wsum[wid] = s;
    __syncthreads();
    if (wid == 0) {
        int ws = wsum[lane];
#pragma unroll
        for (int o = 1; o < 32; o <<= 1) {
            int t = __shfl_up_sync(~0u, ws, o);
            if (lane >= o) ws += t;
        }
        wsum[lane] = ws;
    }
    __syncthreads();
    int excl = s - v + (wid > 0 ? wsum[wid - 1] : 0);
    if (i < n) g_off[i] = excl;
    if (threadIdx.x == 1023) g_bsum[blockIdx.x] = wsum[31];
}

__global__ void __launch_bounds__(128) scan_tops_kernel(int nb) {
    __shared__ int wsum[4];
    int lane = threadIdx.x & 31;
    int wid  = threadIdx.x >> 5;
    int v = (threadIdx.x < nb) ? g_bsum[threadIdx.x] : 0;
    int s = v;
#pragma unroll
    for (int o = 1; o < 32; o <<= 1) {
        int t = __shfl_up_sync(~0u, s, o);
        if (lane >= o) s += t;
    }
    if (lane == 31) wsum[wid] = s;
    __syncthreads();
    int base = 0;
#pragma unroll
    for (int k = 0; k < 4; k++) if (k < wid) base += wsum[k];
    if (threadIdx.x < nb) g_bsum[threadIdx.x] = base + s - v;
}

__global__ void __launch_bounds__(1024) add_offsets_kernel(int n) {
    int i = blockIdx.x * 1024 + threadIdx.x;
    if (i < n) g_cur[i] = g_off[i] + g_bsum[blockIdx.x];
}

__global__ void scatter_kernel(const void* __restrict__ ei,
                               const float* __restrict__ ea, int E, int N) {
    __shared__ int sflag;
    bool idx64 = block_idx64(ei, N, &sflag);
    int e = blockIdx.x * blockDim.x + threadIdx.x;
    if (e >= E) return;
    int s, d;
    if (idx64) {
        const long long* p = (const long long*)ei;
        s = (int)p[e]; d = (int)p[(size_t)E + e];
    } else {
        const int* p = (const int*)ei;
        s = p[e]; d = p[(size_t)E + e];
    }
    int pos = atomicAdd(&g_cur[s], 1);
    g_sd[pos] = make_int2(s, d);
    float4 a0 = *(const float4*)(ea + (size_t)e * 8);
    float4 a1 = *(const float4*)(ea + (size_t)e * 8 + 4);
    *(float4*)(g_eas + (size_t)pos * 8)     = a0;
    *(float4*)(g_eas + (size_t)pos * 8 + 4) = a1;
}

// ---------------- P2: conv2 src-partial per node ----------------
__global__ void __launch_bounds__(256) p2_kernel(int N) {
    int n = blockIdx.x * blockDim.x + threadIdx.x;
    if (n >= N) return;
    const ull* w1p = reinterpret_cast<const ull*>(cw + OC2W1);
    ull H[8];
#pragma unroll
    for (int k = 0; k < 8; k++) H[k] = pk2(cw[OC2B1 + 2*k], cw[OC2B1 + 2*k+1]);
    const float4* ph = (const float4*)(g_h1 + (size_t)n * F);
#pragma unroll
    for (int q = 0; q < 4; q++) {
        float4 v = ph[q];
        float hv[4] = {v.x, v.y, v.z, v.w};
#pragma unroll
        for (int r = 0; r < 4; r++) {
            ull vv = bcast2(hv[r]);
            int i = q * 4 + r;
#pragma unroll
            for (int k = 0; k < 8; k++) H[k] = fma2(vv, w1p[i*8 + k], H[k]);
        }
    }
    ull* out = (ull*)(g_P2 + (size_t)n * F);
#pragma unroll
    for (int k = 0; k < 8; k++) out[k] = H[k];
}

// ---------------- warp-segmented max (shfl scan) + tail atomics ----------------
__device__ __forceinline__ void seg_max_commit(int s, float* o, float* hout) {
    int lane = threadIdx.x & 31;
#pragma unroll
    for (int off = 1; off < 32; off <<= 1) {
        int so = __shfl_up_sync(~0u, s, off);
        bool merge = (lane >= off) && (so == s);
#pragma unroll
        for (int f = 0; f < F; f++) {
            float v = __shfl_up_sync(~0u, o[f], off);
            if (merge) o[f] = fmaxf(o[f], v);
        }
    }
    int snext = __shfl_down_sync(~0u, s, 1);
    bool tail = (lane == 31) || (snext != s);
    if (tail) {
        int* hp = (int*)(hout + (size_t)s * F);
#pragma unroll
        for (int f = 0; f < F; f++)
            atomicMax(hp + f, __float_as_int(fmaxf(o[f], 0.f)));
    }
}

// ---------------- conv edge kernels: one lane = one sorted edge ----------------
__global__ void __launch_bounds__(256) conv1_edge_kernel(const float* __restrict__ x, int E) {
    int p = blockIdx.x * blockDim.x + threadIdx.x;
    p = min(p, E - 1);   // duplicates harmless for max

    const ull* w1p = reinterpret_cast<const ull*>(cw + OC1W1);
    const ull* w2p = reinterpret_cast<const ull*>(cw + OC1W2);

    int2 sd = g_sd[p];
    // inline P1: bias + src rows (x[s] is broadcast-cheap within a segment)
    float4 xi = *(const float4*)(x + (size_t)sd.x * 4);
    float4 xj = *(const float4*)(x + (size_t)sd.y * 4);
    float4 a0 = *(const float4*)(g_eas + (size_t)p * 8);
    float4 a1 = *(const float4*)(g_eas + (size_t)p * 8 + 4);

    ull H[8];
#pragma unroll
    for (int k = 0; k < 8; k++) H[k] = pk2(cw[OC1B1 + 2*k], cw[OC1B1 + 2*k+1]);

    float in[16] = {xi.x, xi.y, xi.z, xi.w, xj.x, xj.y, xj.z, xj.w,
                    a0.x, a0.y, a0.z, a0.w, a1.x, a1.y, a1.z, a1.w};
#pragma unroll
    for (int i = 0; i < 16; i++) {
        ull vv = bcast2(in[i]);
#pragma unroll
        for (int k = 0; k < 8; k++) H[k] = fma2(vv, w1p[i*8 + k], H[k]);
    }

    ull O[8];
#pragma unroll
    for (int k = 0; k < 8; k++) O[k] = pk2(cw[OC1B2 + 2*k], cw[OC1B2 + 2*k+1]);
#pragma unroll
    for (int k = 0; k < 8; k++) {
        float a, b; upk2(H[k], a, b);
        a = fmaxf(a, 0.f); b = fmaxf(b, 0.f);
        ull va = bcast2(a), vb = bcast2(b);
#pragma unroll
        for (int m = 0; m < 8; m++) O[m] = fma2(va, w2p[(2*k)*8 + m], O[m]);
#pragma unroll
        for (int m = 0; m < 8; m++) O[m] = fma2(vb, w2p[(2*k+1)*8 + m], O[m]);
    }
    float o[F];
#pragma unroll
    for (int m = 0; m < 8; m++) upk2(O[m], o[2*m], o[2*m+1]);

    seg_max_commit(sd.x, o, g_h1);
}

__global__ void __launch_bounds__(256) conv2_edge_kernel(int E) {
    int p = blockIdx.x * blockDim.x + threadIdx.x;
    p = min(p, E - 1);

    const ull* w1p = reinterpret_cast<const ull*>(cw + OC2W1);
    const ull* w2p = reinterpret_cast<const ull*>(cw + OC2W2);

    int2 sd = g_sd[p];
    ull H[8];
    {
        const ull* Pp = (const ull*)(g_P2 + (size_t)sd.x * F);
#pragma unroll
        for (int k = 0; k < 8; k++) H[k] = Pp[k];
    }
    float in[24];
    {
        const float4* pd = (const float4*)(g_h1 + (size_t)sd.y * F);
#pragma unroll
        for (int q = 0; q < 4; q++) {
            float4 v = pd[q];
            in[q*4+0] = v.x; in[q*4+1] = v.y; in[q*4+2] = v.z; in[q*4+3] = v.w;
        }
        float4 a0 = *(const float4*)(g_eas + (size_t)p * 8);
        float4 a1 = *(const float4*)(g_eas + (size_t)p * 8 + 4);
        in[16] = a0.x; in[17] = a0.y; in[18] = a0.z; in[19] = a0.w;
        in[20] = a1.x; in[21] = a1.y; in[22] = a1.z; in[23] = a1.w;
    }
#pragma unroll
    for (int i = 0; i < 24; i++) {
        ull vv = bcast2(in[i]);
#pragma unroll
        for (int k = 0; k < 8; k++) H[k] = fma2(vv, w1p[(16+i)*8 + k], H[k]);
    }

    ull O[8];
#pragma unroll
    for (int k = 0; k < 8; k++) O[k] = pk2(cw[OC2B2 + 2*k], cw[OC2B2 + 2*k+1]);
#pragma unroll
    for (int k = 0; k < 8; k++) {
        float a, b; upk2(H[k], a, b);
        a = fmaxf(a, 0.f); b = fmaxf(b, 0.f);
        ull va = bcast2(a), vb = bcast2(b);
#pragma unroll
        for (int m = 0; m < 8; m++) O[m] = fma2(va, w2p[(2*k)*8 + m], O[m]);
#pragma unroll
        for (int m = 0; m < 8; m++) O[m] = fma2(vb, w2p[(2*k+1)*8 + m], O[m]);
    }
    float o[F];
#pragma unroll
    for (int m = 0; m < 8; m++) upk2(O[m], o[2*m], o[2*m+1]);

    seg_max_commit(sd.x, o, g_h2);
}

// ---------------- final node MLP (packed) ----------------
__global__ void __launch_bounds__(256) node_mlp_kernel(float* __restrict__ out, int n) {
    int i = blockIdx.x * blockDim.x + threadIdx.x;
    if (i >= n) return;

    const ull* w1p = reinterpret_cast<const ull*>(cw + OCLW1);

    ull H[8];
#pragma unroll
    for (int k = 0; k < 8; k++) H[k] = pk2(cw[OCLB1 + 2*k], cw[OCLB1 + 2*k+1]);

    const float4* ph = (const float4*)(g_h2 + (size_t)i * F);
#pragma unroll
    for (int q = 0; q < 4; q++) {
        float4 v = ph[q];
        float hv[4] = {v.x, v.y, v.z, v.w};
#pragma unroll
        for (int r = 0; r < 4; r++) {
            ull vv = bcast2(hv[r]);
            int kk = q * 4 + r;
#pragma unroll
            for (int k = 0; k < 8; k++) H[k] = fma2(vv, w1p[kk*8 + k], H[k]);
        }
    }

    float acc = cw[OCLB2];
#pragma unroll
    for (int k = 0; k < 8; k++) {
        float a, b; upk2(H[k], a, b);
        acc += fmaxf(a, 0.f) * cw[OCLW2 + 2*k] + fmaxf(b, 0.f) * cw[OCLW2 + 2*k+1];
    }
    out[i] = acc;
}

// ---------------- launch: fork-join to overlap weight/zero chain with edge chain ----------------
extern "C" void kernel_launch(void* const* d_in, const int* in_sizes, int n_in,
                              void* d_out, int out_size)
{
    const float* x  = (const float*)d_in[0];
    const void*  ei = d_in[1];
    const float* ea = (const float*)d_in[2];

    int N = in_sizes[0] / 4;   // x is [N,4]
    int E = in_sizes[2] / 8;   // edge_attr is [E,8]
    float* out = (float*)d_out;

    // persistent side stream + events (created once; host-side resources only)
    static cudaStream_t sB = nullptr;
    static cudaEvent_t  ev0 = nullptr, evB = nullptr;
    if (sB == nullptr) {
        cudaStreamCreateWithFlags(&sB, cudaStreamNonBlocking);
        cudaEventCreateWithFlags(&ev0, cudaEventDisableTiming);
        cudaEventCreateWithFlags(&evB, cudaEventDisableTiming);
    }

    int eblocks = (E + 255) / 256;
    int sblocks = (N + 1023) / 1024;

    // fork: edge pipeline on sB
    cudaEventRecord(ev0, 0);
    cudaStreamWaitEvent(sB, ev0, 0);
    zero_deg_kernel<<<(N + 255) / 256, 256, 0, sB>>>(N);
    hist_kernel<<<eblocks, 256, 0, sB>>>(ei, E, N);
    scan_blocks_kernel<<<sblocks, 1024, 0, sB>>>(N);
    scan_tops_kernel<<<1, 128, 0, sB>>>(sblocks);
    add_offsets_kernel<<<sblocks, 1024, 0, sB>>>(N);
    scatter_kernel<<<eblocks, 256, 0, sB>>>(ei, ea, E, N);
    cudaEventRecord(evB, sB);

    // main stream: weights + h zeroing (independent of edge pipeline)
    stage_weights_kernel<<<1, 256>>>(
        (const float*)d_in[3],  (const float*)d_in[4],  (const float*)d_in[5],
        (const float*)d_in[6],  (const float*)d_in[7],  (const float*)d_in[8],
        (const float*)d_in[9],  (const float*)d_in[10], (const float*)d_in[11],
        (const float*)d_in[12], (const float*)d_in[13], (const float*)d_in[14]);
    void* stage_addr = nullptr;
    cudaGetSymbolAddress(&stage_addr, g_stage);
    cudaMemcpyToSymbolAsync(cw, stage_addr, CWTOT * sizeof(float), 0,
                            cudaMemcpyDeviceToDevice);
    zero_h_kernel<<<(N * 4 + 255) / 256, 256>>>(N);

    // join
    cudaStreamWaitEvent(0, evB, 0);

    conv1_edge_kernel<<<eblocks, 256>>>(x, E);
    p2_kernel<<<(N + 255) / 256, 256>>>(N);
    conv2_edge_kernel<<<eblocks, 256>>>(E);
    node_mlp_kernel<<<(N + 255) / 256, 256>>>(out, N);
}